// round 14
// baseline (speedup 1.0000x reference)
#include <cuda_runtime.h>
#include <cuda_fp16.h>
#include <cstdint>

// ---------------- Problem constants ----------------
#define NROWS   8192          // B*S = 2*4096
#define DMODEL  1024
#define DFF     2048
#define NHEADS  16
#define DK      64
#define SEQ     4096
#define LN_EPS  1e-6f

// ---------------- Scratch (device globals; no allocation allowed) ----------------
__device__ __half g_xh [NROWS * DMODEL];
__device__ __half g_Wqh[DMODEL * DMODEL];
__device__ __half g_Wkh[DMODEL * DMODEL];
__device__ __half g_Wvh[DMODEL * DMODEL];
__device__ __half g_Woh[DMODEL * DMODEL];
__device__ __half g_W1h[DMODEL * DFF];
__device__ __half g_W2h[DFF * DMODEL];
__device__ __half g_Qh [NROWS * DMODEL];
__device__ __half g_Kh [NROWS * DMODEL];
__device__ __half g_Vh [NROWS * DMODEL];
__device__ __half g_Oh [NROWS * DMODEL];
__device__ __half g_X1h[NROWS * DMODEL];
__device__ __half g_Hh [NROWS * DFF];
__device__ float  g_T1 [NROWS * DMODEL];
__device__ float  g_X1 [NROWS * DMODEL];

// ---------------- helpers ----------------
__device__ __forceinline__ void mma16(float* d, const uint32_t* a, const uint32_t* b) {
    asm volatile(
        "mma.sync.aligned.m16n8k16.row.col.f32.f16.f16.f32 "
        "{%0,%1,%2,%3}, {%4,%5,%6,%7}, {%8,%9}, {%0,%1,%2,%3};"
        : "+f"(d[0]), "+f"(d[1]), "+f"(d[2]), "+f"(d[3])
        : "r"(a[0]), "r"(a[1]), "r"(a[2]), "r"(a[3]), "r"(b[0]), "r"(b[1]));
}
__device__ __forceinline__ void ldsm4(uint32_t* r, uint32_t addr) {
    asm volatile("ldmatrix.sync.aligned.m8n8.x4.shared.b16 {%0,%1,%2,%3}, [%4];"
                 : "=r"(r[0]), "=r"(r[1]), "=r"(r[2]), "=r"(r[3]) : "r"(addr));
}
__device__ __forceinline__ void ldsm4t(uint32_t* r, uint32_t addr) {
    asm volatile("ldmatrix.sync.aligned.m8n8.x4.trans.shared.b16 {%0,%1,%2,%3}, [%4];"
                 : "=r"(r[0]), "=r"(r[1]), "=r"(r[2]), "=r"(r[3]) : "r"(addr));
}
__device__ __forceinline__ uint32_t packh2(float a, float b) {
    __half2 h = __floats2half2_rn(a, b);
    return *(uint32_t*)&h;
}
#define EX2H2(x) asm("ex2.approx.f16x2 %0, %0;" : "+r"(x))

#define CP16(dst_u32, src_ptr) \
    asm volatile("cp.async.cg.shared.global [%0], [%1], 16;" :: "r"(dst_u32), "l"(src_ptr))
#define CP_COMMIT() asm volatile("cp.async.commit_group;" ::: "memory")
#define CP_WAIT1()  asm volatile("cp.async.wait_group 1;" ::: "memory")
#define CP_WAIT0()  asm volatile("cp.async.wait_group 0;" ::: "memory")

// ---------------- fused fp32 -> fp16 conversion (7 regions, 1 launch) ----------------
struct Cvt7 {
    const float* s[7];
    __half*      d[7];
    int          cum[8];
};

__global__ __launch_bounds__(256)
void cvt7_kernel(Cvt7 p)
{
    int i4 = (blockIdx.x * 256 + threadIdx.x) * 4;
    if (i4 >= p.cum[7]) return;
    int r = 0;
    #pragma unroll
    for (int k = 1; k < 7; k++) r += (i4 >= p.cum[k]);
    const int off = i4 - p.cum[r];
    float4 v = *(const float4*)(p.s[r] + off);
    *(__half2*)(p.d[r] + off)     = __floats2half2_rn(v.x, v.y);
    *(__half2*)(p.d[r] + off + 2) = __floats2half2_rn(v.z, v.w);
}

// ---------------- FP16 GEMM: 3-stage cp.async, 8 warps (2x4), 64x32 warp tile, BK=64 ----------------
#define GBM 128
#define GBN 128
#define GBK 64
#define AS_STR_H 72
#define BS_STR_H 136
#define AS_H (GBM * AS_STR_H)              // 9216
#define BS_H (GBK * BS_STR_H)              // 8704
#define STAGE_H (AS_H + BS_H)              // 17920
#define STAGE_B (STAGE_H * 2)              // 35840
#define GSMEM_BYTES (3 * STAGE_B)          // 107520

__device__ __forceinline__
void gemm_core(int N, int K,
               const __half* __restrict__ A,
               const __half* __restrict__ B,
               const float* __restrict__ bias,
               float* __restrict__ C32, __half* __restrict__ C16,
               float scale16, int relu, __half* smem, int bxi, int byi)
{
    const int tid  = threadIdx.x;
    const int warp = tid >> 5;
    const int lane = tid & 31;
    const int grp  = lane >> 2;
    const int tc4  = lane & 3;
    const int wm   = (warp >> 2) * 64;
    const int wn   = (warp & 3) * 32;

    const int rA = tid >> 3;
    const int cA = (tid & 7) * 8;
    const int rB = tid >> 4;
    const int cB = (tid & 15) * 8;

    const __half* Asrc = A + (size_t)(byi * GBM + rA) * K + cA;
    const __half* Bsrc = B + (size_t)rB * N + bxi * GBN + cB;

    const uint32_t smem_u32 = (uint32_t)__cvta_generic_to_shared(smem);
    const uint32_t dA0 = smem_u32 + (rA * AS_STR_H + cA) * 2;
    const uint32_t dB0 = smem_u32 + AS_H * 2 + (rB * BS_STR_H + cB) * 2;

    float acc[4][4][4];
    #pragma unroll
    for (int i = 0; i < 4; i++)
        #pragma unroll
        for (int j = 0; j < 4; j++)
            #pragma unroll
            for (int r = 0; r < 4; r++) acc[i][j][r] = 0.f;

    const int T = K / GBK;

    auto issue = [&](int t, int s) {
        const uint32_t base = (uint32_t)(s * STAGE_B);
        const __half* Ap = Asrc + (size_t)t * GBK;
        const __half* Bp = Bsrc + (size_t)t * GBK * N;
        #pragma unroll
        for (int i = 0; i < 4; i++)
            CP16(dA0 + base + i * (32 * AS_STR_H * 2), Ap + (size_t)i * 32 * K);
        #pragma unroll
        for (int i = 0; i < 4; i++)
            CP16(dB0 + base + i * (16 * BS_STR_H * 2), Bp + (size_t)i * 16 * N);
    };

    issue(0, 0); CP_COMMIT();
    issue(1, 1); CP_COMMIT();

    const int l15 = lane & 15;
    const int l16 = (lane >> 4) * 8;

    int s = 0;
    for (int t = 0; t < T; t++) {
        CP_WAIT1();
        __syncthreads();
        if (t + 2 < T) {
            int sn = s + 2; if (sn >= 3) sn -= 3;
            issue(t + 2, sn);
        }
        CP_COMMIT();

        const uint32_t Abase = smem_u32 + s * STAGE_B;
        const uint32_t Bbase = Abase + AS_H * 2;

        #pragma unroll
        for (int ks = 0; ks < 4; ks++) {
            const int koff = ks * 16;
            uint32_t a[4][4], b[4][2];
            #pragma unroll
            for (int fm = 0; fm < 4; fm++) {
                uint32_t addr = Abase + ((wm + fm * 16 + l15) * AS_STR_H + koff + l16) * 2;
                ldsm4(a[fm], addr);
            }
            #pragma unroll
            for (int p = 0; p < 2; p++) {
                uint32_t r[4];
                uint32_t addr = Bbase + ((koff + l15) * BS_STR_H + wn + p * 16 + l16) * 2;
                ldsm4t(r, addr);
                b[2*p][0] = r[0]; b[2*p][1] = r[1];
                b[2*p+1][0] = r[2]; b[2*p+1][1] = r[3];
            }
            #pragma unroll
            for (int fm = 0; fm < 4; fm++)
                #pragma unroll
                for (int fn = 0; fn < 4; fn++)
                    mma16(acc[fm][fn], a[fm], b[fn]);
        }
        s = (s + 1 == 3) ? 0 : s + 1;
    }

    #pragma unroll
    for (int fm = 0; fm < 4; fm++) {
        #pragma unroll
        for (int fn = 0; fn < 4; fn++) {
            const size_t row0 = (size_t)byi * GBM + wm + fm * 16 + grp;
            const int    col  = bxi * GBN + wn + fn * 8 + 2 * tc4;
            const float bx = bias[col], by = bias[col + 1];
            float2 v0, v1;
            v0.x = acc[fm][fn][0] + bx;  v0.y = acc[fm][fn][1] + by;
            v1.x = acc[fm][fn][2] + bx;  v1.y = acc[fm][fn][3] + by;
            if (relu) {
                v0.x = fmaxf(v0.x, 0.f); v0.y = fmaxf(v0.y, 0.f);
                v1.x = fmaxf(v1.x, 0.f); v1.y = fmaxf(v1.y, 0.f);
            }
            if (C32) {
                *(float2*)(&C32[row0 * N + col])       = v0;
                *(float2*)(&C32[(row0 + 8) * N + col]) = v1;
            }
            if (C16) {
                *(uint32_t*)(&C16[row0 * N + col])       = packh2(v0.x * scale16, v0.y * scale16);
                *(uint32_t*)(&C16[(row0 + 8) * N + col]) = packh2(v1.x * scale16, v1.y * scale16);
            }
        }
    }
}

__global__ __launch_bounds__(256, 2)
void gemm_fp16(int N, int K,
               const __half* __restrict__ A, const __half* __restrict__ B,
               const float* __restrict__ bias,
               float* __restrict__ C32, __half* __restrict__ C16, int relu)
{
    extern __shared__ __half smem_h[];
    gemm_core(N, K, A, B, bias, C32, C16, 1.0f, relu, smem_h, blockIdx.x, blockIdx.y);
}

__global__ __launch_bounds__(256, 2)
void gemm_qkv(int N, int K,
              const __half* __restrict__ A,
              const __half* __restrict__ B0, const __half* __restrict__ B1, const __half* __restrict__ B2,
              const float* __restrict__ b0, const float* __restrict__ b1, const float* __restrict__ b2,
              __half* __restrict__ C0, __half* __restrict__ C1, __half* __restrict__ C2)
{
    extern __shared__ __half smem_h[];
    const int z = blockIdx.z;
    const __half* B  = (z == 0) ? B0 : ((z == 1) ? B1 : B2);
    const float*  bi = (z == 0) ? b0 : ((z == 1) ? b1 : b2);
    __half*       C  = (z == 0) ? C0 : ((z == 1) ? C1 : C2);
    const float   sc = (z == 0) ? (0.125f * 1.4426950408889634f) : 1.0f;
    gemm_core(N, K, A, B, bi, (float*)0, C, sc, 0, smem_h, blockIdx.x, blockIdx.y);
}

// ---------------- FP16 MMA flash attention: cross-tile S/PV software pipeline ----------------
// Iter t computes p(t)=ex2(S_cur), PV(t) from V@stage t%3, and S(t+1) from K@stage (t+1)%3,
// interleaved per j-chunk so the tensor pipe never drains on the ex2 chain.
#define AQ 128
#define AK 64
#define AT_STR 72
#define AT_KFL_H (AK * AT_STR)
#define AT_STAGE_H (2 * AT_KFL_H)
#define AT_STAGE_B (AT_STAGE_H * 2)
#define AT_SMEM_BYTES (3 * AT_STAGE_B)

__global__ __launch_bounds__(128, 2)
void attn_mma_kernel(const __half* __restrict__ Q,
                     const __half* __restrict__ K,
                     const __half* __restrict__ V,
                     __half* __restrict__ O)
{
    extern __shared__ __half smem_h[];

    const int bh = blockIdx.y;
    const int b  = bh >> 4;
    const int h  = bh & 15;
    const int q0 = blockIdx.x * AQ;
    const int tid  = threadIdx.x;
    const int warp = tid >> 5;
    const int lane = tid & 31;
    const int grp  = lane >> 2;
    const int tc4  = lane & 3;
    const int wq   = warp * 32;
    const size_t rowbase = (size_t)b * SEQ;
    const int hcol = h * DK;

    uint32_t qa0[4][4], qa1[4][4];
    {
        const size_t r00 = (rowbase + q0 + wq + grp) * DMODEL + hcol;
        #pragma unroll
        for (int kt = 0; kt < 4; kt++) {
            const int c = kt * 16 + 2 * tc4;
            qa0[kt][0] = *(const uint32_t*)(Q + r00 + c);
            qa0[kt][1] = *(const uint32_t*)(Q + r00 + 8 * DMODEL + c);
            qa0[kt][2] = *(const uint32_t*)(Q + r00 + c + 8);
            qa0[kt][3] = *(const uint32_t*)(Q + r00 + 8 * DMODEL + c + 8);
            qa1[kt][0] = *(const uint32_t*)(Q + r00 + 16 * DMODEL + c);
            qa1[kt][1] = *(const uint32_t*)(Q + r00 + 24 * DMODEL + c);
            qa1[kt][2] = *(const uint32_t*)(Q + r00 + 16 * DMODEL + c + 8);
            qa1[kt][3] = *(const uint32_t*)(Q + r00 + 24 * DMODEL + c + 8);
        }
    }

    const uint32_t smem_u32 = (uint32_t)__cvta_generic_to_shared(smem_h);
    const int rK = tid >> 3;
    const int cK = (tid & 7) * 8;

    auto issue = [&](int t, int s) {
        const uint32_t base = smem_u32 + (uint32_t)(s * AT_STAGE_B);
        const size_t grow = (rowbase + (size_t)t * AK + rK) * DMODEL + hcol + cK;
        const __half* Kp = K + grow;
        const __half* Vp = V + grow;
        #pragma unroll
        for (int i = 0; i < 4; i++)
            CP16(base + ((rK + 16 * i) * AT_STR + cK) * 2, Kp + (size_t)(16 * i) * DMODEL);
        #pragma unroll
        for (int i = 0; i < 4; i++)
            CP16(base + (AT_KFL_H + (rK + 16 * i) * AT_STR + cK) * 2, Vp + (size_t)(16 * i) * DMODEL);
    };

    float o0[8][4], o1[8][4], lo0[4], lo1[4];
    #pragma unroll
    for (int nt = 0; nt < 8; nt++)
        #pragma unroll
        for (int r = 0; r < 4; r++) { o0[nt][r] = 0.f; o1[nt][r] = 0.f; }
    #pragma unroll
    for (int r = 0; r < 4; r++) { lo0[r] = 0.f; lo1[r] = 0.f; }

    const uint32_t ones2 = 0x3C003C00u;
    const uint32_t vb1[2] = { ones2, ones2 };

    const int T = SEQ / AK;   // 64
    const int l15 = lane & 15;
    const int l16 = (lane >> 4) * 8;
    const int km  = lane >> 3;
    const int krow = (km >> 1) * 8 + (lane & 7);
    const int kchk = (km & 1) * 8;

    float sc0[8][4], sc1[8][4];   // S(t) (current)
    float sn0[8][4], sn1[8][4];   // S(t+1) (next, built during iter t)

    // ---- prologue: load tiles 0,1; compute S(0) ----
    issue(0, 0); CP_COMMIT();
    issue(1, 1); CP_COMMIT();
    CP_WAIT1();                   // tile 0 complete
    __syncthreads();
    {
        const uint32_t Kbase = smem_u32;   // stage 0
        #pragma unroll
        for (int nt = 0; nt < 8; nt++)
            #pragma unroll
            for (int r = 0; r < 4; r++) { sc0[nt][r] = 0.f; sc1[nt][r] = 0.f; }
        #pragma unroll
        for (int kt = 0; kt < 4; kt++) {
            const int koff = kt * 16;
            #pragma unroll
            for (int g = 0; g < 4; g++) {
                uint32_t r[4];
                uint32_t addr = Kbase + ((g * 16 + krow) * AT_STR + koff + kchk) * 2;
                ldsm4(r, addr);
                mma16(sc0[2*g],   qa0[kt], r + 0);
                mma16(sc0[2*g+1], qa0[kt], r + 2);
                mma16(sc1[2*g],   qa1[kt], r + 0);
                mma16(sc1[2*g+1], qa1[kt], r + 2);
            }
        }
    }

    for (int t = 0; t < T; t++) {
        CP_WAIT0();               // all outstanding tiles (incl. t+1) complete
        __syncthreads();          // visibility + stage-reuse safety
        if (t + 2 < T) {
            int sn = t + 2; sn -= (sn / 3) * 3;
            issue(t + 2, sn);
        }
        CP_COMMIT();

        const int   st    = t % 3;
        const int   stn   = (t + 1 < T) ? ((t + 1) % 3) : st;
        const uint32_t Vbase  = smem_u32 + st  * AT_STAGE_B + AT_KFL_H * 2;
        const uint32_t KbaseN = smem_u32 + stn * AT_STAGE_B;
        const bool  haveNext = (t + 1 < T);

        if (haveNext) {
            #pragma unroll
            for (int nt = 0; nt < 8; nt++)
                #pragma unroll
                for (int r = 0; r < 4; r++) { sn0[nt][r] = 0.f; sn1[nt][r] = 0.f; }
        }

        #pragma unroll
        for (int j = 0; j < 4; j++) {
            // p(t) chunk j -> fp16 A-frags
            uint32_t pa0[4], pa1[4];
            pa0[0] = packh2(sc0[2*j][0],   sc0[2*j][1]);   EX2H2(pa0[0]);
            pa0[1] = packh2(sc0[2*j][2],   sc0[2*j][3]);   EX2H2(pa0[1]);
            pa0[2] = packh2(sc0[2*j+1][0], sc0[2*j+1][1]); EX2H2(pa0[2]);
            pa0[3] = packh2(sc0[2*j+1][2], sc0[2*j+1][3]); EX2H2(pa0[3]);
            pa1[0] = packh2(sc1[2*j][0],   sc1[2*j][1]);   EX2H2(pa1[0]);
            pa1[1] = packh2(sc1[2*j][2],   sc1[2*j][3]);   EX2H2(pa1[1]);
            pa1[2] = packh2(sc1[2*j+1][0], sc1[2*j+1][1]); EX2H2(pa1[2]);
            pa1[3] = packh2(sc1[2*j+1][2], sc1[2*j+1][3]); EX2H2(pa1[3]);

            mma16(lo0, pa0, vb1);
            mma16(lo1, pa1, vb1);

            // S(t+1), kt = j (independent of PV stream; fills tensor pipe)
            if (haveNext) {
                const int koff = j * 16;
                #pragma unroll
                for (int g = 0; g < 4; g++) {
                    uint32_t r[4];
                    uint32_t addr = KbaseN + ((g * 16 + krow) * AT_STR + koff + kchk) * 2;
                    ldsm4(r, addr);
                    mma16(sn0[2*g],   qa0[j], r + 0);
                    mma16(sn0[2*g+1], qa0[j], r + 2);
                    mma16(sn1[2*g],   qa1[j], r + 0);
                    mma16(sn1[2*g+1], qa1[j], r + 2);
                }
            }

            // PV(t) chunk j
            uint32_t vb[8][2];
            #pragma unroll
            for (int p = 0; p < 4; p++) {
                uint32_t r[4];
                uint32_t addr = Vbase + ((j * 16 + l15) * AT_STR + p * 16 + l16) * 2;
                ldsm4t(r, addr);
                vb[2*p][0] = r[0]; vb[2*p][1] = r[1];
                vb[2*p+1][0] = r[2]; vb[2*p+1][1] = r[3];
            }
            #pragma unroll
            for (int nt = 0; nt < 8; nt++) {
                mma16(o0[nt], pa0, vb[nt]);
                mma16(o1[nt], pa1, vb[nt]);
            }
        }

        if (haveNext) {
            #pragma unroll
            for (int nt = 0; nt < 8; nt++)
                #pragma unroll
                for (int r = 0; r < 4; r++) { sc0[nt][r] = sn0[nt][r]; sc1[nt][r] = sn1[nt][r]; }
        }
    }

    const float i0 = 1.f / lo0[0], i1 = 1.f / lo0[2];
    const float i2 = 1.f / lo1[0], i3 = 1.f / lo1[2];

    const size_t row0 = rowbase + q0 + wq + grp;
    #pragma unroll
    for (int nt = 0; nt < 8; nt++) {
        const int col = hcol + nt * 8 + 2 * tc4;
        *(uint32_t*)(&O[row0 * DMODEL + col])        = packh2(o0[nt][0] * i0, o0[nt][1] * i0);
        *(uint32_t*)(&O[(row0 + 8) * DMODEL + col])  = packh2(o0[nt][2] * i1, o0[nt][3] * i1);
        *(uint32_t*)(&O[(row0 + 16) * DMODEL + col]) = packh2(o1[nt][0] * i2, o1[nt][1] * i2);
        *(uint32_t*)(&O[(row0 + 24) * DMODEL + col]) = packh2(o1[nt][2] * i3, o1[nt][3] * i3);
    }
}

// ---------------- Residual add + LayerNorm ----------------
__global__ __launch_bounds__(256)
void add_ln_kernel(const float* __restrict__ X,
                   const float* __restrict__ Y,
                   const float* __restrict__ alpha,
                   const float* __restrict__ beta,
                   float* __restrict__ out,
                   __half* __restrict__ out16)
{
    const int row = blockIdx.x;
    const int tid = threadIdx.x;
    const size_t base = (size_t)row * DMODEL;
    const int c = tid * 4;

    float4 a = *(const float4*)(&X[base + c]);
    float4 b = *(const float4*)(&Y[base + c]);
    float v0 = a.x + b.x, v1 = a.y + b.y, v2 = a.z + b.z, v3 = a.w + b.w;

    float sum = v0 + v1 + v2 + v3;
    float sq  = v0*v0 + v1*v1 + v2*v2 + v3*v3;

    #pragma unroll
    for (int o = 16; o > 0; o >>= 1) {
        sum += __shfl_xor_sync(0xffffffffu, sum, o);
        sq  += __shfl_xor_sync(0xffffffffu, sq,  o);
    }
    __shared__ float ssum[8], ssq[8];
    const int warp = tid >> 5, lane = tid & 31;
    if (lane == 0) { ssum[warp] = sum; ssq[warp] = sq; }
    __syncthreads();
    if (warp == 0) {
        sum = (lane < 8) ? ssum[lane] : 0.f;
        sq  = (lane < 8) ? ssq[lane]  : 0.f;
        #pragma unroll
        for (int o = 4; o > 0; o >>= 1) {
            sum += __shfl_xor_sync(0xffffffffu, sum, o);
            sq  += __shfl_xor_sync(0xffffffffu, sq,  o);
        }
        if (lane == 0) { ssum[0] = sum; ssq[0] = sq; }
    }
    __syncthreads();
    sum = ssum[0]; sq = ssq[0];

    const float mean = sum * (1.f / DMODEL);
    float var = (sq - (float)DMODEL * mean * mean) * (1.f / (DMODEL - 1));
    var = fmaxf(var, 0.f);
    const float r = 1.f / (sqrtf(var) + LN_EPS);

    float4 al = *(const float4*)(&alpha[c]);
    float4 be = *(const float4*)(&beta[c]);
    float4 o4;
    o4.x = al.x * (v0 - mean) * r + be.x;
    o4.y = al.y * (v1 - mean) * r + be.y;
    o4.z = al.z * (v2 - mean) * r + be.z;
    o4.w = al.w * (v3 - mean) * r + be.w;
    *(float4*)(&out[base + c]) = o4;
    if (out16) {
        *(__half2*)(&out16[base + c])     = __floats2half2_rn(o4.x, o4.y);
        *(__half2*)(&out16[base + c + 2]) = __floats2half2_rn(o4.z, o4.w);
    }
}

// ---------------- Launch ----------------
extern "C" void kernel_launch(void* const* d_in, const int* in_sizes, int n_in,
                              void* d_out, int out_size)
{
    const float* x   = (const float*)d_in[0];
    const float* Wq  = (const float*)d_in[1];
    const float* bq  = (const float*)d_in[2];
    const float* Wk  = (const float*)d_in[3];
    const float* bk  = (const float*)d_in[4];
    const float* Wv  = (const float*)d_in[5];
    const float* bv  = (const float*)d_in[6];
    const float* Wo  = (const float*)d_in[7];
    const float* bo  = (const float*)d_in[8];
    const float* W1  = (const float*)d_in[9];
    const float* b1  = (const float*)d_in[10];
    const float* W2  = (const float*)d_in[11];
    const float* b2  = (const float*)d_in[12];
    const float* al1 = (const float*)d_in[13];
    const float* be1 = (const float*)d_in[14];
    const float* al2 = (const float*)d_in[15];
    const float* be2 = (const float*)d_in[16];

    __half *xh, *Wqh, *Wkh, *Wvh, *Woh, *W1h, *W2h, *Qh, *Kh, *Vh, *Oh, *X1h, *Hh;
    float *T1, *X1;
    cudaGetSymbolAddress((void**)&xh,  g_xh);
    cudaGetSymbolAddress((void**)&Wqh, g_Wqh);
    cudaGetSymbolAddress((void**)&Wkh, g_Wkh);
    cudaGetSymbolAddress((void**)&Wvh, g_Wvh);
    cudaGetSymbolAddress((void**)&Woh, g_Woh);
    cudaGetSymbolAddress((void**)&W1h, g_W1h);
    cudaGetSymbolAddress((void**)&W2h, g_W2h);
    cudaGetSymbolAddress((void**)&Qh,  g_Qh);
    cudaGetSymbolAddress((void**)&Kh,  g_Kh);
    cudaGetSymbolAddress((void**)&Vh,  g_Vh);
    cudaGetSymbolAddress((void**)&Oh,  g_Oh);
    cudaGetSymbolAddress((void**)&X1h, g_X1h);
    cudaGetSymbolAddress((void**)&Hh,  g_Hh);
    cudaGetSymbolAddress((void**)&T1,  g_T1);
    cudaGetSymbolAddress((void**)&X1,  g_X1);

    cudaFuncSetAttribute(gemm_fp16, cudaFuncAttributeMaxDynamicSharedMemorySize, GSMEM_BYTES);
    cudaFuncSetAttribute(gemm_qkv,  cudaFuncAttributeMaxDynamicSharedMemorySize, GSMEM_BYTES);
    cudaFuncSetAttribute(attn_mma_kernel, cudaFuncAttributeMaxDynamicSharedMemorySize, AT_SMEM_BYTES);

    Cvt7 cp;
    cp.s[0] = x;  cp.d[0] = xh;
    cp.s[1] = Wq; cp.d[1] = Wqh;
    cp.s[2] = Wk; cp.d[2] = Wkh;
    cp.s[3] = Wv; cp.d[3] = Wvh;
    cp.s[4] = Wo; cp.d[4] = Woh;
    cp.s[5] = W1; cp.d[5] = W1h;
    cp.s[6] = W2; cp.d[6] = W2h;
    const int sizes[7] = {NROWS * DMODEL, DMODEL * DMODEL, DMODEL * DMODEL, DMODEL * DMODEL,
                          DMODEL * DMODEL, DMODEL * DFF, DFF * DMODEL};
    cp.cum[0] = 0;
    for (int i = 0; i < 7; i++) cp.cum[i + 1] = cp.cum[i] + sizes[i];
    cvt7_kernel<<<(cp.cum[7] / 4 + 255) / 256, 256>>>(cp);

    const dim3 blk(256);
    const dim3 gD(DMODEL / GBN, NROWS / GBM);        // (8, 64)
    const dim3 gQKV(DMODEL / GBN, NROWS / GBM, 3);   // (8, 64, 3)
    const dim3 gF(DFF / GBN,    NROWS / GBM);        // (16, 64)

    gemm_qkv<<<gQKV, blk, GSMEM_BYTES>>>(DMODEL, DMODEL, xh,
                                         Wqh, Wkh, Wvh, bq, bk, bv, Qh, Kh, Vh);

    attn_mma_kernel<<<dim3(SEQ / AQ, 2 * NHEADS), 128, AT_SMEM_BYTES>>>(Qh, Kh, Vh, Oh);

    gemm_fp16<<<gD, blk, GSMEM_BYTES>>>(DMODEL, DMODEL, Oh, Woh, bo, T1, (__half*)0, 0);
    add_ln_kernel<<<NROWS, 256>>>(x, T1, al1, be1, X1, X1h);

    gemm_fp16<<<gF, blk, GSMEM_BYTES>>>(DFF, DMODEL, X1h, W1h, b1, (float*)0, Hh, 1);
    gemm_fp16<<<gD, blk, GSMEM_BYTES>>>(DMODEL, DFF, Hh, W2h, b2, T1, (__half*)0, 0);
    add_ln_kernel<<<NROWS, 256>>>(X1, T1, al2, be2, (float*)d_out, (__half*)0);
}

// round 15
// speedup vs baseline: 1.1822x; 1.1822x over previous
#include <cuda_runtime.h>
#include <cuda_fp16.h>
#include <cstdint>

// ---------------- Problem constants ----------------
#define NROWS   8192          // B*S = 2*4096
#define DMODEL  1024
#define DFF     2048
#define NHEADS  16
#define DK      64
#define SEQ     4096
#define LN_EPS  1e-6f

// ---------------- Scratch (device globals; no allocation allowed) ----------------
__device__ __half g_xh [NROWS * DMODEL];
__device__ __half g_Wqh[DMODEL * DMODEL];
__device__ __half g_Wkh[DMODEL * DMODEL];
__device__ __half g_Wvh[DMODEL * DMODEL];
__device__ __half g_Woh[DMODEL * DMODEL];
__device__ __half g_W1h[DMODEL * DFF];
__device__ __half g_W2h[DFF * DMODEL];
__device__ __half g_Qh [NROWS * DMODEL];
__device__ __half g_Kh [NROWS * DMODEL];
__device__ __half g_Vh [NROWS * DMODEL];
__device__ __half g_Oh [NROWS * DMODEL];
__device__ __half g_X1h[NROWS * DMODEL];
__device__ __half g_Hh [NROWS * DFF];
__device__ float  g_T1 [NROWS * DMODEL];
__device__ float  g_X1 [NROWS * DMODEL];

// ---------------- helpers ----------------
__device__ __forceinline__ void mma16(float* d, const uint32_t* a, const uint32_t* b) {
    asm volatile(
        "mma.sync.aligned.m16n8k16.row.col.f32.f16.f16.f32 "
        "{%0,%1,%2,%3}, {%4,%5,%6,%7}, {%8,%9}, {%0,%1,%2,%3};"
        : "+f"(d[0]), "+f"(d[1]), "+f"(d[2]), "+f"(d[3])
        : "r"(a[0]), "r"(a[1]), "r"(a[2]), "r"(a[3]), "r"(b[0]), "r"(b[1]));
}
__device__ __forceinline__ void ldsm4(uint32_t* r, uint32_t addr) {
    asm volatile("ldmatrix.sync.aligned.m8n8.x4.shared.b16 {%0,%1,%2,%3}, [%4];"
                 : "=r"(r[0]), "=r"(r[1]), "=r"(r[2]), "=r"(r[3]) : "r"(addr));
}
__device__ __forceinline__ void ldsm4t(uint32_t* r, uint32_t addr) {
    asm volatile("ldmatrix.sync.aligned.m8n8.x4.trans.shared.b16 {%0,%1,%2,%3}, [%4];"
                 : "=r"(r[0]), "=r"(r[1]), "=r"(r[2]), "=r"(r[3]) : "r"(addr));
}
__device__ __forceinline__ uint32_t packh2(float a, float b) {
    __half2 h = __floats2half2_rn(a, b);
    return *(uint32_t*)&h;
}
#define EX2H2(x) asm("ex2.approx.f16x2 %0, %0;" : "+r"(x))

#define CP16(dst_u32, src_ptr) \
    asm volatile("cp.async.cg.shared.global [%0], [%1], 16;" :: "r"(dst_u32), "l"(src_ptr))
#define CP_COMMIT() asm volatile("cp.async.commit_group;" ::: "memory")
#define CP_WAIT1()  asm volatile("cp.async.wait_group 1;" ::: "memory")

// ---------------- fused fp32 -> fp16 conversion (7 regions, 1 launch) ----------------
struct Cvt7 {
    const float* s[7];
    __half*      d[7];
    int          cum[8];
};

__global__ __launch_bounds__(256)
void cvt7_kernel(Cvt7 p)
{
    int i4 = (blockIdx.x * 256 + threadIdx.x) * 4;
    if (i4 >= p.cum[7]) return;
    int r = 0;
    #pragma unroll
    for (int k = 1; k < 7; k++) r += (i4 >= p.cum[k]);
    const int off = i4 - p.cum[r];
    float4 v = *(const float4*)(p.s[r] + off);
    *(__half2*)(p.d[r] + off)     = __floats2half2_rn(v.x, v.y);
    *(__half2*)(p.d[r] + off + 2) = __floats2half2_rn(v.z, v.w);
}

// ---------------- FP16 GEMM: 3-stage cp.async, 4 warps, 64x64 warp tile, BK=64 ----------------
#define GBM 128
#define GBN 128
#define GBK 64
#define AS_STR_H 72                        // halves; 144B rows, ldmatrix conflict-free
#define BS_STR_H 136                       // halves; 272B rows, conflict-free
#define AS_H (GBM * AS_STR_H)              // 9216
#define BS_H (GBK * BS_STR_H)              // 8704
#define STAGE_H (AS_H + BS_H)              // 17920
#define STAGE_B (STAGE_H * 2)              // 35840
#define GSMEM_BYTES (3 * STAGE_B)          // 107520

__device__ __forceinline__
void gemm_core(int N, int K,
               const __half* __restrict__ A,
               const __half* __restrict__ B,
               const float* __restrict__ bias,
               float* __restrict__ C32, __half* __restrict__ C16,
               float scale16, int relu, __half* smem, int bxi, int byi)
{
    const int tid  = threadIdx.x;
    const int warp = tid >> 5;           // 0..3
    const int lane = tid & 31;
    const int grp  = lane >> 2;
    const int tc4  = lane & 3;
    const int wm   = (warp >> 1) * 64;
    const int wn   = (warp & 1) * 64;

    // cp.async (128 threads): A 1024 chunks, B 1024 chunks; 8+8 per thread
    const int rA = tid >> 3;             // 0..15 (+16*i)
    const int cA = (tid & 7) * 8;        // halves
    const int rB = tid >> 4;             // 0..7 (+8*i)
    const int cB = (tid & 15) * 8;       // halves

    const __half* Asrc = A + (size_t)(byi * GBM + rA) * K + cA;
    const __half* Bsrc = B + (size_t)rB * N + bxi * GBN + cB;

    const uint32_t smem_u32 = (uint32_t)__cvta_generic_to_shared(smem);
    const uint32_t dA0 = smem_u32 + (rA * AS_STR_H + cA) * 2;
    const uint32_t dB0 = smem_u32 + AS_H * 2 + (rB * BS_STR_H + cB) * 2;

    float acc[4][8][4];
    #pragma unroll
    for (int i = 0; i < 4; i++)
        #pragma unroll
        for (int j = 0; j < 8; j++)
            #pragma unroll
            for (int r = 0; r < 4; r++) acc[i][j][r] = 0.f;

    const int T = K / GBK;

    auto issue = [&](int t, int s) {
        const uint32_t base = (uint32_t)(s * STAGE_B);
        const __half* Ap = Asrc + (size_t)t * GBK;
        const __half* Bp = Bsrc + (size_t)t * GBK * N;
        #pragma unroll
        for (int i = 0; i < 8; i++)
            CP16(dA0 + base + i * (16 * AS_STR_H * 2), Ap + (size_t)i * 16 * K);
        #pragma unroll
        for (int i = 0; i < 8; i++)
            CP16(dB0 + base + i * (8 * BS_STR_H * 2), Bp + (size_t)i * 8 * N);
    };

    issue(0, 0); CP_COMMIT();
    issue(1, 1); CP_COMMIT();

    const int l15 = lane & 15;
    const int l16 = (lane >> 4) * 8;

    int s = 0;
    for (int t = 0; t < T; t++) {
        CP_WAIT1();
        __syncthreads();
        if (t + 2 < T) {
            int sn = s + 2; if (sn >= 3) sn -= 3;
            issue(t + 2, sn);
        }
        CP_COMMIT();

        const uint32_t Abase = smem_u32 + s * STAGE_B;
        const uint32_t Bbase = Abase + AS_H * 2;

        #pragma unroll
        for (int ks = 0; ks < 4; ks++) {
            const int koff = ks * 16;
            uint32_t a[4][4], b[8][2];
            #pragma unroll
            for (int fm = 0; fm < 4; fm++) {
                uint32_t addr = Abase + ((wm + fm * 16 + l15) * AS_STR_H + koff + l16) * 2;
                ldsm4(a[fm], addr);
            }
            #pragma unroll
            for (int p = 0; p < 4; p++) {
                uint32_t r[4];
                uint32_t addr = Bbase + ((koff + l15) * BS_STR_H + wn + p * 16 + l16) * 2;
                ldsm4t(r, addr);
                b[2*p][0] = r[0]; b[2*p][1] = r[1];
                b[2*p+1][0] = r[2]; b[2*p+1][1] = r[3];
            }
            #pragma unroll
            for (int fm = 0; fm < 4; fm++)
                #pragma unroll
                for (int fn = 0; fn < 8; fn++)
                    mma16(acc[fm][fn], a[fm], b[fn]);
        }
        s = (s + 1 == 3) ? 0 : s + 1;
    }

    #pragma unroll
    for (int fm = 0; fm < 4; fm++) {
        #pragma unroll
        for (int fn = 0; fn < 8; fn++) {
            const size_t row0 = (size_t)byi * GBM + wm + fm * 16 + grp;
            const int    col  = bxi * GBN + wn + fn * 8 + 2 * tc4;
            const float bx = bias[col], by = bias[col + 1];
            float2 v0, v1;
            v0.x = acc[fm][fn][0] + bx;  v0.y = acc[fm][fn][1] + by;
            v1.x = acc[fm][fn][2] + bx;  v1.y = acc[fm][fn][3] + by;
            if (relu) {
                v0.x = fmaxf(v0.x, 0.f); v0.y = fmaxf(v0.y, 0.f);
                v1.x = fmaxf(v1.x, 0.f); v1.y = fmaxf(v1.y, 0.f);
            }
            if (C32) {
                *(float2*)(&C32[row0 * N + col])       = v0;
                *(float2*)(&C32[(row0 + 8) * N + col]) = v1;
            }
            if (C16) {
                *(uint32_t*)(&C16[row0 * N + col])       = packh2(v0.x * scale16, v0.y * scale16);
                *(uint32_t*)(&C16[(row0 + 8) * N + col]) = packh2(v1.x * scale16, v1.y * scale16);
            }
        }
    }
}

__global__ __launch_bounds__(128, 2)
void gemm_fp16(int N, int K,
               const __half* __restrict__ A, const __half* __restrict__ B,
               const float* __restrict__ bias,
               float* __restrict__ C32, __half* __restrict__ C16, int relu)
{
    extern __shared__ __half smem_h[];
    gemm_core(N, K, A, B, bias, C32, C16, 1.0f, relu, smem_h, blockIdx.x, blockIdx.y);
}

__global__ __launch_bounds__(128, 2)
void gemm_qkv(int N, int K,
              const __half* __restrict__ A,
              const __half* __restrict__ B0, const __half* __restrict__ B1, const __half* __restrict__ B2,
              const float* __restrict__ b0, const float* __restrict__ b1, const float* __restrict__ b2,
              __half* __restrict__ C0, __half* __restrict__ C1, __half* __restrict__ C2)
{
    extern __shared__ __half smem_h[];
    const int z = blockIdx.z;
    const __half* B  = (z == 0) ? B0 : ((z == 1) ? B1 : B2);
    const float*  bi = (z == 0) ? b0 : ((z == 1) ? b1 : b2);
    __half*       C  = (z == 0) ? C0 : ((z == 1) ? C1 : C2);
    const float   sc = (z == 0) ? (0.125f * 1.4426950408889634f) : 1.0f;
    gemm_core(N, K, A, B, bi, (float*)0, C, sc, 0, smem_h, blockIdx.x, blockIdx.y);
}

// ---------------- FP16 MMA flash attention (R13, known-good) ----------------
#define AQ 128
#define AK 64
#define AT_STR 72
#define AT_KFL_H (AK * AT_STR)
#define AT_STAGE_H (2 * AT_KFL_H)
#define AT_STAGE_B (AT_STAGE_H * 2)
#define AT_SMEM_BYTES (3 * AT_STAGE_B)

__global__ __launch_bounds__(128, 2)
void attn_mma_kernel(const __half* __restrict__ Q,
                     const __half* __restrict__ K,
                     const __half* __restrict__ V,
                     __half* __restrict__ O)
{
    extern __shared__ __half smem_h[];

    const int bh = blockIdx.y;
    const int b  = bh >> 4;
    const int h  = bh & 15;
    const int q0 = blockIdx.x * AQ;
    const int tid  = threadIdx.x;
    const int warp = tid >> 5;
    const int lane = tid & 31;
    const int grp  = lane >> 2;
    const int tc4  = lane & 3;
    const int wq   = warp * 32;
    const size_t rowbase = (size_t)b * SEQ;
    const int hcol = h * DK;

    uint32_t qa0[4][4], qa1[4][4];
    {
        const size_t r00 = (rowbase + q0 + wq + grp) * DMODEL + hcol;
        #pragma unroll
        for (int kt = 0; kt < 4; kt++) {
            const int c = kt * 16 + 2 * tc4;
            qa0[kt][0] = *(const uint32_t*)(Q + r00 + c);
            qa0[kt][1] = *(const uint32_t*)(Q + r00 + 8 * DMODEL + c);
            qa0[kt][2] = *(const uint32_t*)(Q + r00 + c + 8);
            qa0[kt][3] = *(const uint32_t*)(Q + r00 + 8 * DMODEL + c + 8);
            qa1[kt][0] = *(const uint32_t*)(Q + r00 + 16 * DMODEL + c);
            qa1[kt][1] = *(const uint32_t*)(Q + r00 + 24 * DMODEL + c);
            qa1[kt][2] = *(const uint32_t*)(Q + r00 + 16 * DMODEL + c + 8);
            qa1[kt][3] = *(const uint32_t*)(Q + r00 + 24 * DMODEL + c + 8);
        }
    }

    const uint32_t smem_u32 = (uint32_t)__cvta_generic_to_shared(smem_h);
    const int rK = tid >> 3;
    const int cK = (tid & 7) * 8;

    auto issue = [&](int t, int s) {
        const uint32_t base = smem_u32 + (uint32_t)(s * AT_STAGE_B);
        const size_t grow = (rowbase + (size_t)t * AK + rK) * DMODEL + hcol + cK;
        const __half* Kp = K + grow;
        const __half* Vp = V + grow;
        #pragma unroll
        for (int i = 0; i < 4; i++)
            CP16(base + ((rK + 16 * i) * AT_STR + cK) * 2, Kp + (size_t)(16 * i) * DMODEL);
        #pragma unroll
        for (int i = 0; i < 4; i++)
            CP16(base + (AT_KFL_H + (rK + 16 * i) * AT_STR + cK) * 2, Vp + (size_t)(16 * i) * DMODEL);
    };

    float o0[8][4], o1[8][4], lo0[4], lo1[4];
    #pragma unroll
    for (int nt = 0; nt < 8; nt++)
        #pragma unroll
        for (int r = 0; r < 4; r++) { o0[nt][r] = 0.f; o1[nt][r] = 0.f; }
    #pragma unroll
    for (int r = 0; r < 4; r++) { lo0[r] = 0.f; lo1[r] = 0.f; }

    const uint32_t ones2 = 0x3C003C00u;
    const uint32_t vb1[2] = { ones2, ones2 };

    const int T = SEQ / AK;
    issue(0, 0); CP_COMMIT();
    issue(1, 1); CP_COMMIT();

    const int l15 = lane & 15;
    const int l16 = (lane >> 4) * 8;
    const int km  = lane >> 3;
    const int krow = (km >> 1) * 8 + (lane & 7);
    const int kchk = (km & 1) * 8;

    int s = 0;
    for (int t = 0; t < T; t++) {
        CP_WAIT1();
        __syncthreads();
        if (t + 2 < T) {
            int sn = s + 2; if (sn >= 3) sn -= 3;
            issue(t + 2, sn);
        }
        CP_COMMIT();

        const uint32_t Kbase = smem_u32 + s * AT_STAGE_B;
        const uint32_t Vbase = Kbase + AT_KFL_H * 2;

        float s0[8][4], s1[8][4];
        #pragma unroll
        for (int nt = 0; nt < 8; nt++)
            #pragma unroll
            for (int r = 0; r < 4; r++) { s0[nt][r] = 0.f; s1[nt][r] = 0.f; }

        #pragma unroll
        for (int kt = 0; kt < 4; kt++) {
            const int koff = kt * 16;
            #pragma unroll
            for (int g = 0; g < 4; g++) {
                uint32_t r[4];
                uint32_t addr = Kbase + ((g * 16 + krow) * AT_STR + koff + kchk) * 2;
                ldsm4(r, addr);
                mma16(s0[2*g],   qa0[kt], r + 0);
                mma16(s0[2*g+1], qa0[kt], r + 2);
                mma16(s1[2*g],   qa1[kt], r + 0);
                mma16(s1[2*g+1], qa1[kt], r + 2);
            }
        }

        #pragma unroll
        for (int j = 0; j < 4; j++) {
            uint32_t pa0[4], pa1[4];
            pa0[0] = packh2(s0[2*j][0],   s0[2*j][1]);   EX2H2(pa0[0]);
            pa0[1] = packh2(s0[2*j][2],   s0[2*j][3]);   EX2H2(pa0[1]);
            pa0[2] = packh2(s0[2*j+1][0], s0[2*j+1][1]); EX2H2(pa0[2]);
            pa0[3] = packh2(s0[2*j+1][2], s0[2*j+1][3]); EX2H2(pa0[3]);
            pa1[0] = packh2(s1[2*j][0],   s1[2*j][1]);   EX2H2(pa1[0]);
            pa1[1] = packh2(s1[2*j][2],   s1[2*j][3]);   EX2H2(pa1[1]);
            pa1[2] = packh2(s1[2*j+1][0], s1[2*j+1][1]); EX2H2(pa1[2]);
            pa1[3] = packh2(s1[2*j+1][2], s1[2*j+1][3]); EX2H2(pa1[3]);

            mma16(lo0, pa0, vb1);
            mma16(lo1, pa1, vb1);

            uint32_t vb[8][2];
            #pragma unroll
            for (int p = 0; p < 4; p++) {
                uint32_t r[4];
                uint32_t addr = Vbase + ((j * 16 + l15) * AT_STR + p * 16 + l16) * 2;
                ldsm4t(r, addr);
                vb[2*p][0] = r[0]; vb[2*p][1] = r[1];
                vb[2*p+1][0] = r[2]; vb[2*p+1][1] = r[3];
            }
            #pragma unroll
            for (int nt = 0; nt < 8; nt++) {
                mma16(o0[nt], pa0, vb[nt]);
                mma16(o1[nt], pa1, vb[nt]);
            }
        }
        s = (s + 1 == 3) ? 0 : s + 1;
    }

    const float i0 = 1.f / lo0[0], i1 = 1.f / lo0[2];
    const float i2 = 1.f / lo1[0], i3 = 1.f / lo1[2];

    const size_t row0 = rowbase + q0 + wq + grp;
    #pragma unroll
    for (int nt = 0; nt < 8; nt++) {
        const int col = hcol + nt * 8 + 2 * tc4;
        *(uint32_t*)(&O[row0 * DMODEL + col])        = packh2(o0[nt][0] * i0, o0[nt][1] * i0);
        *(uint32_t*)(&O[(row0 + 8) * DMODEL + col])  = packh2(o0[nt][2] * i1, o0[nt][3] * i1);
        *(uint32_t*)(&O[(row0 + 16) * DMODEL + col]) = packh2(o1[nt][0] * i2, o1[nt][1] * i2);
        *(uint32_t*)(&O[(row0 + 24) * DMODEL + col]) = packh2(o1[nt][2] * i3, o1[nt][3] * i3);
    }
}

// ---------------- Residual add + LayerNorm ----------------
__global__ __launch_bounds__(256)
void add_ln_kernel(const float* __restrict__ X,
                   const float* __restrict__ Y,
                   const float* __restrict__ alpha,
                   const float* __restrict__ beta,
                   float* __restrict__ out,
                   __half* __restrict__ out16)
{
    const int row = blockIdx.x;
    const int tid = threadIdx.x;
    const size_t base = (size_t)row * DMODEL;
    const int c = tid * 4;

    float4 a = *(const float4*)(&X[base + c]);
    float4 b = *(const float4*)(&Y[base + c]);
    float v0 = a.x + b.x, v1 = a.y + b.y, v2 = a.z + b.z, v3 = a.w + b.w;

    float sum = v0 + v1 + v2 + v3;
    float sq  = v0*v0 + v1*v1 + v2*v2 + v3*v3;

    #pragma unroll
    for (int o = 16; o > 0; o >>= 1) {
        sum += __shfl_xor_sync(0xffffffffu, sum, o);
        sq  += __shfl_xor_sync(0xffffffffu, sq,  o);
    }
    __shared__ float ssum[8], ssq[8];
    const int warp = tid >> 5, lane = tid & 31;
    if (lane == 0) { ssum[warp] = sum; ssq[warp] = sq; }
    __syncthreads();
    if (warp == 0) {
        sum = (lane < 8) ? ssum[lane] : 0.f;
        sq  = (lane < 8) ? ssq[lane]  : 0.f;
        #pragma unroll
        for (int o = 4; o > 0; o >>= 1) {
            sum += __shfl_xor_sync(0xffffffffu, sum, o);
            sq  += __shfl_xor_sync(0xffffffffu, sq,  o);
        }
        if (lane == 0) { ssum[0] = sum; ssq[0] = sq; }
    }
    __syncthreads();
    sum = ssum[0]; sq = ssq[0];

    const float mean = sum * (1.f / DMODEL);
    float var = (sq - (float)DMODEL * mean * mean) * (1.f / (DMODEL - 1));
    var = fmaxf(var, 0.f);
    const float r = 1.f / (sqrtf(var) + LN_EPS);

    float4 al = *(const float4*)(&alpha[c]);
    float4 be = *(const float4*)(&beta[c]);
    float4 o4;
    o4.x = al.x * (v0 - mean) * r + be.x;
    o4.y = al.y * (v1 - mean) * r + be.y;
    o4.z = al.z * (v2 - mean) * r + be.z;
    o4.w = al.w * (v3 - mean) * r + be.w;
    *(float4*)(&out[base + c]) = o4;
    if (out16) {
        *(__half2*)(&out16[base + c])     = __floats2half2_rn(o4.x, o4.y);
        *(__half2*)(&out16[base + c + 2]) = __floats2half2_rn(o4.z, o4.w);
    }
}

// ---------------- Launch ----------------
extern "C" void kernel_launch(void* const* d_in, const int* in_sizes, int n_in,
                              void* d_out, int out_size)
{
    const float* x   = (const float*)d_in[0];
    const float* Wq  = (const float*)d_in[1];
    const float* bq  = (const float*)d_in[2];
    const float* Wk  = (const float*)d_in[3];
    const float* bk  = (const float*)d_in[4];
    const float* Wv  = (const float*)d_in[5];
    const float* bv  = (const float*)d_in[6];
    const float* Wo  = (const float*)d_in[7];
    const float* bo  = (const float*)d_in[8];
    const float* W1  = (const float*)d_in[9];
    const float* b1  = (const float*)d_in[10];
    const float* W2  = (const float*)d_in[11];
    const float* b2  = (const float*)d_in[12];
    const float* al1 = (const float*)d_in[13];
    const float* be1 = (const float*)d_in[14];
    const float* al2 = (const float*)d_in[15];
    const float* be2 = (const float*)d_in[16];

    __half *xh, *Wqh, *Wkh, *Wvh, *Woh, *W1h, *W2h, *Qh, *Kh, *Vh, *Oh, *X1h, *Hh;
    float *T1, *X1;
    cudaGetSymbolAddress((void**)&xh,  g_xh);
    cudaGetSymbolAddress((void**)&Wqh, g_Wqh);
    cudaGetSymbolAddress((void**)&Wkh, g_Wkh);
    cudaGetSymbolAddress((void**)&Wvh, g_Wvh);
    cudaGetSymbolAddress((void**)&Woh, g_Woh);
    cudaGetSymbolAddress((void**)&W1h, g_W1h);
    cudaGetSymbolAddress((void**)&W2h, g_W2h);
    cudaGetSymbolAddress((void**)&Qh,  g_Qh);
    cudaGetSymbolAddress((void**)&Kh,  g_Kh);
    cudaGetSymbolAddress((void**)&Vh,  g_Vh);
    cudaGetSymbolAddress((void**)&Oh,  g_Oh);
    cudaGetSymbolAddress((void**)&X1h, g_X1h);
    cudaGetSymbolAddress((void**)&Hh,  g_Hh);
    cudaGetSymbolAddress((void**)&T1,  g_T1);
    cudaGetSymbolAddress((void**)&X1,  g_X1);

    cudaFuncSetAttribute(gemm_fp16, cudaFuncAttributeMaxDynamicSharedMemorySize, GSMEM_BYTES);
    cudaFuncSetAttribute(gemm_qkv,  cudaFuncAttributeMaxDynamicSharedMemorySize, GSMEM_BYTES);
    cudaFuncSetAttribute(attn_mma_kernel, cudaFuncAttributeMaxDynamicSharedMemorySize, AT_SMEM_BYTES);

    Cvt7 cp;
    cp.s[0] = x;  cp.d[0] = xh;
    cp.s[1] = Wq; cp.d[1] = Wqh;
    cp.s[2] = Wk; cp.d[2] = Wkh;
    cp.s[3] = Wv; cp.d[3] = Wvh;
    cp.s[4] = Wo; cp.d[4] = Woh;
    cp.s[5] = W1; cp.d[5] = W1h;
    cp.s[6] = W2; cp.d[6] = W2h;
    const int sizes[7] = {NROWS * DMODEL, DMODEL * DMODEL, DMODEL * DMODEL, DMODEL * DMODEL,
                          DMODEL * DMODEL, DMODEL * DFF, DFF * DMODEL};
    cp.cum[0] = 0;
    for (int i = 0; i < 7; i++) cp.cum[i + 1] = cp.cum[i] + sizes[i];
    cvt7_kernel<<<(cp.cum[7] / 4 + 255) / 256, 256>>>(cp);

    const dim3 blk(128);
    const dim3 gD(DMODEL / GBN, NROWS / GBM);        // (8, 64)
    const dim3 gQKV(DMODEL / GBN, NROWS / GBM, 3);   // (8, 64, 3)
    const dim3 gF(DFF / GBN,    NROWS / GBM);        // (16, 64)

    gemm_qkv<<<gQKV, blk, GSMEM_BYTES>>>(DMODEL, DMODEL, xh,
                                         Wqh, Wkh, Wvh, bq, bk, bv, Qh, Kh, Vh);

    attn_mma_kernel<<<dim3(SEQ / AQ, 2 * NHEADS), 128, AT_SMEM_BYTES>>>(Qh, Kh, Vh, Oh);

    gemm_fp16<<<gD, blk, GSMEM_BYTES>>>(DMODEL, DMODEL, Oh, Woh, bo, T1, (__half*)0, 0);
    add_ln_kernel<<<NROWS, 256>>>(x, T1, al1, be1, X1, X1h);

    gemm_fp16<<<gF, blk, GSMEM_BYTES>>>(DFF, DMODEL, X1h, W1h, b1, (float*)0, Hh, 1);
    gemm_fp16<<<gD, blk, GSMEM_BYTES>>>(DMODEL, DFF, Hh, W2h, b2, T1, (__half*)0, 0);
    add_ln_kernel<<<NROWS, 256>>>(X1, T1, al2, be2, (float*)d_out, (__half*)0);
}